// round 1
// baseline (speedup 1.0000x reference)
#include <cuda_runtime.h>
#include <cuda_bf16.h>
#include <math.h>

#define B 4
#define N 50000
#define E 800000
#define FIN 128
#define FOUT 64
#define ALPHA 0.2f
#define NEG_BIG (-9000000000000000.0f)

// ---------------- device scratch (static globals; no allocation) -------------
__device__ float g_h[(size_t)B * N * FOUT];        // 51.2 MB  projected features
__device__ float g_f1[B * N];                      // h @ a1
__device__ float g_f2[B * N];                      // h @ a2
__device__ int   g_counts[B * N];                  // per-src edge counts
__device__ int   g_offsets[B * (N + 1)];           // CSR row offsets (per batch)
__device__ int   g_cursor[B * N];                  // scatter cursors
__device__ int   g_sorted_dst[(size_t)B * E];      // dst sorted by src

// ---------------- utility: zero counts ---------------------------------------
__global__ void zero_counts_kernel() {
    int i = blockIdx.x * blockDim.x + threadIdx.x;
    if (i < B * N) g_counts[i] = 0;
}

// ---------------- GEMM: h = X @ W  (M=B*N=200000, K=128, N=64) ---------------
// 64x64 tile, BK=64 (two k-tiles), 256 threads, 4x4 micro-tile per thread.
__global__ __launch_bounds__(256) void gemm_kernel(const float* __restrict__ X,
                                                   const float* __restrict__ W) {
    __shared__ float As[64][64];   // As[k][m]  (transposed X tile)
    __shared__ float Bs[64][64];   // Bs[k][n]

    const int tid = threadIdx.x;
    const int block_row = blockIdx.x * 64;            // 3125 blocks exactly
    const int tx = tid & 15;                          // 0..15 -> n0 = tx*4
    const int ty = tid >> 4;                          // 0..15 -> m0 = ty*4
    const int n0 = tx * 4;
    const int m0 = ty * 4;

    float acc[4][4];
#pragma unroll
    for (int i = 0; i < 4; i++)
#pragma unroll
        for (int j = 0; j < 4; j++) acc[i][j] = 0.0f;

    const float4* X4 = (const float4*)X;   // row-major: row*32 float4 per row
    const float4* W4 = (const float4*)W;   // row-major: k*16 float4 per row

    for (int kt = 0; kt < 2; kt++) {
        // load X tile transposed: 64 rows x 64 cols -> 1024 float4, 4 per thread
#pragma unroll
        for (int it = 0; it < 4; it++) {
            int i = tid + it * 256;             // 0..1023
            int row = i & 63;
            int kq  = i >> 6;                   // 0..15 (float4 index within 64 k)
            float4 v = X4[(size_t)(block_row + row) * 32 + kt * 16 + kq];
            As[kq * 4 + 0][row] = v.x;
            As[kq * 4 + 1][row] = v.y;
            As[kq * 4 + 2][row] = v.z;
            As[kq * 4 + 3][row] = v.w;
        }
        // load W tile: direct copy, 1024 float4
#pragma unroll
        for (int it = 0; it < 4; it++) {
            int i = tid + it * 256;
            ((float4*)&Bs[0][0])[i] = W4[kt * 1024 + i];
        }
        __syncthreads();

#pragma unroll 8
        for (int k = 0; k < 64; k++) {
            float4 a4 = *(const float4*)&As[k][m0];
            float4 b4 = *(const float4*)&Bs[k][n0];
            float av[4] = {a4.x, a4.y, a4.z, a4.w};
            float bv[4] = {b4.x, b4.y, b4.z, b4.w};
#pragma unroll
            for (int i = 0; i < 4; i++)
#pragma unroll
                for (int j = 0; j < 4; j++) acc[i][j] += av[i] * bv[j];
        }
        __syncthreads();
    }

#pragma unroll
    for (int i = 0; i < 4; i++) {
        float4 o = make_float4(acc[i][0], acc[i][1], acc[i][2], acc[i][3]);
        *(float4*)&g_h[(size_t)(block_row + m0 + i) * FOUT + n0] = o;
    }
}

// ---------------- f1 = h@a1, f2 = h@a2 (one warp per row) --------------------
__global__ void f12_kernel(const float* __restrict__ a) {
    int w = (blockIdx.x * blockDim.x + threadIdx.x) >> 5;
    int lane = threadIdx.x & 31;
    if (w >= B * N) return;
    float2 hv = ((const float2*)g_h)[(size_t)w * 32 + lane];
    float2 a1 = ((const float2*)a)[lane];        // a[0..63]
    float2 a2 = ((const float2*)a)[32 + lane];   // a[64..127]
    float s1 = hv.x * a1.x + hv.y * a1.y;
    float s2 = hv.x * a2.x + hv.y * a2.y;
#pragma unroll
    for (int o = 16; o > 0; o >>= 1) {
        s1 += __shfl_xor_sync(0xffffffffu, s1, o);
        s2 += __shfl_xor_sync(0xffffffffu, s2, o);
    }
    if (lane == 0) {
        g_f1[w] = s1;
        g_f2[w] = s2;
    }
}

// ---------------- histogram of src -------------------------------------------
__global__ void hist_kernel(const int* __restrict__ edges) {
    int idx = blockIdx.x * blockDim.x + threadIdx.x;
    if (idx >= B * E) return;
    int b = idx / E;
    int e = idx - b * E;
    int src = edges[(size_t)b * 2 * E + e];
    atomicAdd(&g_counts[b * N + src], 1);
}

// ---------------- per-batch exclusive scan (one block per batch) -------------
__global__ __launch_bounds__(1024) void scan_kernel() {
    const int b = blockIdx.x;
    const int tid = threadIdx.x;
    const int lane = tid & 31, wid = tid >> 5;
    __shared__ int wsum[32];
    __shared__ int carry_s;
    if (tid == 0) carry_s = 0;
    __syncthreads();

    for (int base = 0; base < N; base += 1024) {
        int i = base + tid;
        int v = (i < N) ? g_counts[b * N + i] : 0;
        int x = v;
#pragma unroll
        for (int o = 1; o < 32; o <<= 1) {
            int y = __shfl_up_sync(0xffffffffu, x, o);
            if (lane >= o) x += y;
        }
        if (lane == 31) wsum[wid] = x;
        __syncthreads();
        if (wid == 0) {
            int ws = wsum[lane];
#pragma unroll
            for (int o = 1; o < 32; o <<= 1) {
                int y = __shfl_up_sync(0xffffffffu, ws, o);
                if (lane >= o) ws += y;
            }
            wsum[lane] = ws;   // inclusive over warp sums
        }
        __syncthreads();
        int warp_prefix = (wid > 0) ? wsum[wid - 1] : 0;
        int excl = carry_s + warp_prefix + (x - v);
        if (i < N) {
            g_offsets[b * (N + 1) + i] = excl;
            g_cursor[b * N + i] = excl;
        }
        __syncthreads();
        if (tid == 0) carry_s += wsum[31];
        __syncthreads();
    }
    if (tid == 0) g_offsets[b * (N + 1) + N] = carry_s;
}

// ---------------- scatter dst into CSR buckets -------------------------------
__global__ void scatter_kernel(const int* __restrict__ edges) {
    int idx = blockIdx.x * blockDim.x + threadIdx.x;
    if (idx >= B * E) return;
    int b = idx / E;
    int e = idx - b * E;
    int src = edges[(size_t)b * 2 * E + e];
    int dst = edges[(size_t)b * 2 * E + E + e];
    int pos = atomicAdd(&g_cursor[b * N + src], 1);
    g_sorted_dst[(size_t)b * E + pos] = dst;
}

// ---------------- aggregation: one warp per (b, node) ------------------------
__global__ __launch_bounds__(256) void aggregate_kernel(float* __restrict__ out) {
    int w = (blockIdx.x * blockDim.x + threadIdx.x) >> 5;
    int lane = threadIdx.x & 31;
    if (w >= B * N) return;
    int b = w / N;
    int i = w - b * N;

    int start = g_offsets[b * (N + 1) + i];
    int end   = g_offsets[b * (N + 1) + i + 1];
    float f1i = g_f1[w];

    const float2* __restrict__ hb = (const float2*)(g_h + (size_t)b * N * FOUT);
    const float*  __restrict__ f2b = g_f2 + (size_t)b * N;
    const int*    __restrict__ sd  = g_sorted_dst + (size_t)b * E;

    float accx = 0.0f, accy = 0.0f, rowsum = 0.0f;

    for (int e = start; e < end; e++) {
        int dst = sd[e];                        // same for all lanes -> broadcast
        float s = f1i + f2b[dst];
        float t = (s > 0.0f) ? s : ALPHA * s;   // leaky_relu
        float we = __expf(-t);
        rowsum += we;
        float2 hv = hb[(size_t)dst * 32 + lane];
        accx = fmaf(we, hv.x, accx);
        accy = fmaf(we, hv.y, accy);
    }

    float inv = 1.0f / rowsum;
    float rx = accx * inv;
    float ry = accy * inv;
    if (isnan(rx)) rx = NEG_BIG;
    if (isnan(ry)) ry = NEG_BIG;
    // elu
    rx = (rx > 0.0f) ? rx : expm1f(rx);
    ry = (ry > 0.0f) ? ry : expm1f(ry);

    ((float2*)out)[(size_t)w * 32 + lane] = make_float2(rx, ry);
}

// ---------------- launch ------------------------------------------------------
extern "C" void kernel_launch(void* const* d_in, const int* in_sizes, int n_in,
                              void* d_out, int out_size) {
    const float* X     = (const float*)d_in[0];   // (B, N, FIN)
    const int*   edges = (const int*)d_in[1];     // (B, 2, E)
    const float* W     = (const float*)d_in[2];   // (FIN, FOUT)
    const float* a     = (const float*)d_in[3];   // (1, 2*FOUT)
    float* out = (float*)d_out;                   // (B, N, FOUT)

    // 1. zero counts
    zero_counts_kernel<<<(B * N + 255) / 256, 256>>>();
    // 2. histogram of src
    hist_kernel<<<(B * E + 255) / 256, 256>>>(edges);
    // 3. projection GEMM
    gemm_kernel<<<(B * N) / 64, 256>>>(X, W);
    // 4. attention dot products
    f12_kernel<<<(B * N * 32 + 255) / 256, 256>>>(a);
    // 5. CSR offsets (one block per batch)
    scan_kernel<<<B, 1024>>>();
    // 6. scatter dst by src
    scatter_kernel<<<(B * E + 255) / 256, 256>>>(edges);
    // 7. aggregate + normalize + elu
    aggregate_kernel<<<(B * N * 32 + 255) / 256, 256>>>(out);
}

// round 2
// speedup vs baseline: 1.2088x; 1.2088x over previous
#include <cuda_runtime.h>
#include <cuda_bf16.h>
#include <math.h>

#define B 4
#define N 50000
#define E 800000
#define FIN 128
#define FOUT 64
#define ALPHA 0.2f
#define NEG_BIG (-9000000000000000.0f)

#define NCHUNK 49              // ceil(50000/1024)
#define TOTAL_ROWS (B * N)     // 200000

// ---------------- device scratch (static globals; no allocation) -------------
__device__ float g_h[(size_t)B * N * FOUT];        // 51.2 MB  projected features
__device__ float g_f1[B * N];
__device__ float g_f2[B * N];
__device__ int   g_counts[B * N];
__device__ int   g_offsets[B * (N + 1)];
__device__ int   g_cursor[B * N];
__device__ int   g_sorted_dst[(size_t)B * E];
__device__ int   g_chunksum[B * NCHUNK];
__device__ int   g_chunkbase[B * NCHUNK];

// ---------------- zero counts --------------------------------------------------
__global__ void zero_counts_kernel() {
    int i = blockIdx.x * blockDim.x + threadIdx.x;
    if (i < B * N) g_counts[i] = 0;
}

// ---------------- GEMM (128x64 tile, 8x4 micro) + fused f1/f2 ----------------
__global__ __launch_bounds__(256) void gemm_f12_kernel(const float* __restrict__ X,
                                                       const float* __restrict__ W,
                                                       const float* __restrict__ a) {
    __shared__ float As[64][128];   // As[k][m]
    __shared__ float Bs[64][64];    // Bs[k][n]

    const int tid = threadIdx.x;
    const int block_row = blockIdx.x * 128;          // 1563 blocks, last partial
    const int tx = tid & 15;                         // n0 = tx*4
    const int ty = tid >> 4;                         // m0 = ty*8
    const int n0 = tx * 4;
    const int m0 = ty * 8;

    float acc[8][4];
#pragma unroll
    for (int i = 0; i < 8; i++)
#pragma unroll
        for (int j = 0; j < 4; j++) acc[i][j] = 0.0f;

    const float4* X4 = (const float4*)X;   // row: 32 float4
    const float4* W4 = (const float4*)W;   // 128*16 float4 total

    for (int kt = 0; kt < 2; kt++) {
        // A tile: 128 rows x 64 k = 2048 float4, 8 per thread (transposed store)
#pragma unroll
        for (int it = 0; it < 8; it++) {
            int i = tid + it * 256;                  // 0..2047
            int row = i & 127;
            int kq  = i >> 7;                        // 0..15
            int rg  = block_row + row;
            if (rg > TOTAL_ROWS - 1) rg = TOTAL_ROWS - 1;
            float4 v = X4[(size_t)rg * 32 + kt * 16 + kq];
            As[kq * 4 + 0][row] = v.x;
            As[kq * 4 + 1][row] = v.y;
            As[kq * 4 + 2][row] = v.z;
            As[kq * 4 + 3][row] = v.w;
        }
        // B tile: 64x64 = 1024 float4, 4 per thread
#pragma unroll
        for (int it = 0; it < 4; it++) {
            int i = tid + it * 256;
            ((float4*)&Bs[0][0])[i] = W4[kt * 1024 + i];
        }
        __syncthreads();

#pragma unroll 4
        for (int k = 0; k < 64; k++) {
            float4 a0 = *(const float4*)&As[k][m0];
            float4 a1 = *(const float4*)&As[k][m0 + 4];
            float4 b4 = *(const float4*)&Bs[k][n0];
            float av[8] = {a0.x, a0.y, a0.z, a0.w, a1.x, a1.y, a1.z, a1.w};
            float bv[4] = {b4.x, b4.y, b4.z, b4.w};
#pragma unroll
            for (int i = 0; i < 8; i++)
#pragma unroll
                for (int j = 0; j < 4; j++) acc[i][j] = fmaf(av[i], bv[j], acc[i][j]);
        }
        __syncthreads();
    }

    // attention vector slices for this thread's 4 columns
    float a1c[4], a2c[4];
#pragma unroll
    for (int j = 0; j < 4; j++) {
        a1c[j] = a[n0 + j];
        a2c[j] = a[FOUT + n0 + j];
    }

#pragma unroll
    for (int i = 0; i < 8; i++) {
        int r = block_row + m0 + i;
        float p1 = acc[i][0] * a1c[0] + acc[i][1] * a1c[1] +
                   acc[i][2] * a1c[2] + acc[i][3] * a1c[3];
        float p2 = acc[i][0] * a2c[0] + acc[i][1] * a2c[1] +
                   acc[i][2] * a2c[2] + acc[i][3] * a2c[3];
        // reduce across the 16 tx lanes (xor masks stay within 16-lane halves)
#pragma unroll
        for (int o = 8; o > 0; o >>= 1) {
            p1 += __shfl_xor_sync(0xffffffffu, p1, o);
            p2 += __shfl_xor_sync(0xffffffffu, p2, o);
        }
        if (r < TOTAL_ROWS) {
            *(float4*)&g_h[(size_t)r * FOUT + n0] =
                make_float4(acc[i][0], acc[i][1], acc[i][2], acc[i][3]);
            if (tx == 0) {
                g_f1[r] = p1;
                g_f2[r] = p2;
            }
        }
    }
}

// ---------------- histogram of src -------------------------------------------
__global__ void hist_kernel(const int* __restrict__ edges) {
    int idx = blockIdx.x * blockDim.x + threadIdx.x;
    if (idx >= B * E) return;
    int b = idx / E;
    int e = idx - b * E;
    int src = edges[(size_t)b * 2 * E + e];
    atomicAdd(&g_counts[b * N + src], 1);
}

// ---------------- scan phase A: per-chunk local exclusive scan ----------------
__global__ __launch_bounds__(256) void scanA_kernel() {
    const int b = blockIdx.x / NCHUNK;
    const int c = blockIdx.x - b * NCHUNK;
    const int tid = threadIdx.x;
    const int lane = tid & 31, wid = tid >> 5;
    __shared__ int wsum[8];
    __shared__ int blk_total;

    int base = c * 1024 + tid * 4;
    int v[4];
#pragma unroll
    for (int k = 0; k < 4; k++) {
        int i = base + k;
        v[k] = (i < N) ? g_counts[b * N + i] : 0;
    }
    int s1 = v[0] + v[1];
    int s2 = s1 + v[2];
    int tsum = s2 + v[3];

    // warp inclusive scan of tsum
    int x = tsum;
#pragma unroll
    for (int o = 1; o < 32; o <<= 1) {
        int y = __shfl_up_sync(0xffffffffu, x, o);
        if (lane >= o) x += y;
    }
    if (lane == 31) wsum[wid] = x;
    __syncthreads();
    if (tid < 8) {
        int ws = wsum[tid];
#pragma unroll
        for (int o = 1; o < 8; o <<= 1) {
            int y = __shfl_up_sync(0xffu, ws, o);
            if (tid >= o) ws += y;
        }
        wsum[tid] = ws;
        if (tid == 7) blk_total = ws;
    }
    __syncthreads();
    int excl = (wid > 0 ? wsum[wid - 1] : 0) + (x - tsum);

    int o0 = excl;
    int o1 = excl + v[0];
    int o2 = excl + s1;
    int o3 = excl + s2;
    int outv[4] = {o0, o1, o2, o3};
#pragma unroll
    for (int k = 0; k < 4; k++) {
        int i = base + k;
        if (i < N) g_offsets[b * (N + 1) + i] = outv[k];
    }
    if (tid == 0) g_chunksum[b * NCHUNK + c] = blk_total;
}

// ---------------- scan phase B: scan chunk sums (one block per batch) ---------
__global__ __launch_bounds__(64) void scanB_kernel() {
    const int b = blockIdx.x;
    const int tid = threadIdx.x;
    const int lane = tid & 31, wid = tid >> 5;
    __shared__ int w0sum;
    int v = (tid < NCHUNK) ? g_chunksum[b * NCHUNK + tid] : 0;
    int x = v;
#pragma unroll
    for (int o = 1; o < 32; o <<= 1) {
        int y = __shfl_up_sync(0xffffffffu, x, o);
        if (lane >= o) x += y;
    }
    if (tid == 31) w0sum = x;
    __syncthreads();
    if (wid == 1) x += w0sum;
    if (tid < NCHUNK) g_chunkbase[b * NCHUNK + tid] = x - v;
    if (tid == NCHUNK - 1) g_offsets[b * (N + 1) + N] = x;
}

// ---------------- scan phase C: add chunk bases, write cursor -----------------
__global__ __launch_bounds__(256) void scanC_kernel() {
    const int b = blockIdx.x / NCHUNK;
    const int c = blockIdx.x - b * NCHUNK;
    const int tid = threadIdx.x;
    int base = g_chunkbase[b * NCHUNK + c];
    int i0 = c * 1024 + tid * 4;
#pragma unroll
    for (int k = 0; k < 4; k++) {
        int i = i0 + k;
        if (i < N) {
            int o = g_offsets[b * (N + 1) + i] + base;
            g_offsets[b * (N + 1) + i] = o;
            g_cursor[b * N + i] = o;
        }
    }
}

// ---------------- scatter dst into CSR buckets --------------------------------
__global__ void scatter_kernel(const int* __restrict__ edges) {
    int idx = blockIdx.x * blockDim.x + threadIdx.x;
    if (idx >= B * E) return;
    int b = idx / E;
    int e = idx - b * E;
    int src = edges[(size_t)b * 2 * E + e];
    int dst = edges[(size_t)b * 2 * E + E + e];
    int pos = atomicAdd(&g_cursor[b * N + src], 1);
    g_sorted_dst[(size_t)b * E + pos] = dst;
}

// ---------------- aggregation: one warp per (b, node), chunked MLP -----------
__global__ __launch_bounds__(256) void aggregate_kernel(float* __restrict__ out) {
    int w = (blockIdx.x * blockDim.x + threadIdx.x) >> 5;
    int lane = threadIdx.x & 31;
    if (w >= B * N) return;
    int b = w / N;
    int i = w - b * N;

    int start = g_offsets[b * (N + 1) + i];
    int end   = g_offsets[b * (N + 1) + i + 1];
    float f1i = g_f1[w];

    const float2* __restrict__ hb  = (const float2*)(g_h + (size_t)b * N * FOUT);
    const float*  __restrict__ f2b = g_f2 + (size_t)b * N;
    const int*    __restrict__ sd  = g_sorted_dst + (size_t)b * E;

    float accx = 0.0f, accy = 0.0f, rowsum = 0.0f;

    for (int e = start; e < end; e += 32) {
        int cnt = end - e;
        if (cnt > 32) cnt = 32;
        bool act = lane < cnt;
        int   myDst = act ? sd[e + lane] : 0;
        float s = f1i + (act ? f2b[myDst] : 0.0f);
        float t = (s > 0.0f) ? s : ALPHA * s;
        float myWe = act ? __expf(-t) : 0.0f;
        // warp-reduce the chunk's weight sum (all lanes get it)
        float wsum = myWe;
#pragma unroll
        for (int o = 16; o > 0; o >>= 1) wsum += __shfl_xor_sync(0xffffffffu, wsum, o);
        rowsum += wsum;
        // gather + accumulate; iterations independent -> high MLP
        for (int j = 0; j < cnt; j++) {
            float we  = __shfl_sync(0xffffffffu, myWe, j);
            int   dst = __shfl_sync(0xffffffffu, myDst, j);
            float2 hv = hb[(size_t)dst * 32 + lane];
            accx = fmaf(we, hv.x, accx);
            accy = fmaf(we, hv.y, accy);
        }
    }

    float inv = 1.0f / rowsum;
    float rx = accx * inv;
    float ry = accy * inv;
    if (isnan(rx)) rx = NEG_BIG;
    if (isnan(ry)) ry = NEG_BIG;
    rx = (rx > 0.0f) ? rx : expm1f(rx);
    ry = (ry > 0.0f) ? ry : expm1f(ry);

    ((float2*)out)[(size_t)w * 32 + lane] = make_float2(rx, ry);
}

// ---------------- launch -------------------------------------------------------
extern "C" void kernel_launch(void* const* d_in, const int* in_sizes, int n_in,
                              void* d_out, int out_size) {
    const float* X     = (const float*)d_in[0];   // (B, N, FIN)
    const int*   edges = (const int*)d_in[1];     // (B, 2, E)
    const float* W     = (const float*)d_in[2];   // (FIN, FOUT)
    const float* a     = (const float*)d_in[3];   // (1, 2*FOUT)
    float* out = (float*)d_out;                   // (B, N, FOUT)

    zero_counts_kernel<<<(B * N + 255) / 256, 256>>>();
    hist_kernel<<<(B * E + 255) / 256, 256>>>(edges);
    gemm_f12_kernel<<<(TOTAL_ROWS + 127) / 128, 256>>>(X, W, a);
    scanA_kernel<<<B * NCHUNK, 256>>>();
    scanB_kernel<<<B, 64>>>();
    scanC_kernel<<<B * NCHUNK, 256>>>();
    scatter_kernel<<<(B * E + 255) / 256, 256>>>(edges);
    aggregate_kernel<<<(B * N * 32 + 255) / 256, 256>>>(out);
}

// round 3
// speedup vs baseline: 1.2657x; 1.0471x over previous
#include <cuda_runtime.h>
#include <cuda_bf16.h>
#include <math.h>

#define B 4
#define N 50000
#define E 800000
#define FIN 128
#define FOUT 64
#define ALPHA 0.2f
#define NEG_BIG (-9000000000000000.0f)

#define NCHUNK 49              // ceil(50000/1024)
#define TOTAL_ROWS (B * N)     // 200000

// ---------------- device scratch (static globals; no allocation) -------------
__device__ float g_h[(size_t)B * N * FOUT];        // 51.2 MB  projected features
__device__ float g_f1[B * N];
__device__ float g_f2[B * N];
__device__ int   g_counts[B * N];
__device__ int   g_offsets[B * (N + 1)];
__device__ int   g_cursor[B * N];
__device__ int   g_sorted_dst[(size_t)B * E];
__device__ int   g_chunksum[B * NCHUNK];
__device__ int   g_chunkbase[B * NCHUNK];

// ---------------- zero counts --------------------------------------------------
__global__ void zero_counts_kernel() {
    int i = blockIdx.x * blockDim.x + threadIdx.x;
    if (i < B * N) g_counts[i] = 0;
}

// ---------------- GEMM (128x64 tile, 8x4 micro) + fused f1/f2 ----------------
__global__ __launch_bounds__(256) void gemm_f12_kernel(const float* __restrict__ X,
                                                       const float* __restrict__ W,
                                                       const float* __restrict__ a) {
    __shared__ float As[64][128];   // As[k][m]
    __shared__ float Bs[64][64];    // Bs[k][n]

    const int tid = threadIdx.x;
    const int block_row = blockIdx.x * 128;
    const int tx = tid & 15;                         // n0 = tx*4
    const int ty = tid >> 4;                         // m0 = ty*8
    const int n0 = tx * 4;
    const int m0 = ty * 8;

    float acc[8][4];
#pragma unroll
    for (int i = 0; i < 8; i++)
#pragma unroll
        for (int j = 0; j < 4; j++) acc[i][j] = 0.0f;

    const float4* X4 = (const float4*)X;   // row: 32 float4
    const float4* W4 = (const float4*)W;

    for (int kt = 0; kt < 2; kt++) {
#pragma unroll
        for (int it = 0; it < 8; it++) {
            int i = tid + it * 256;                  // 0..2047
            int row = i & 127;
            int kq  = i >> 7;                        // 0..15
            int rg  = block_row + row;
            if (rg > TOTAL_ROWS - 1) rg = TOTAL_ROWS - 1;
            float4 v = X4[(size_t)rg * 32 + kt * 16 + kq];
            As[kq * 4 + 0][row] = v.x;
            As[kq * 4 + 1][row] = v.y;
            As[kq * 4 + 2][row] = v.z;
            As[kq * 4 + 3][row] = v.w;
        }
#pragma unroll
        for (int it = 0; it < 4; it++) {
            int i = tid + it * 256;
            ((float4*)&Bs[0][0])[i] = W4[kt * 1024 + i];
        }
        __syncthreads();

#pragma unroll 4
        for (int k = 0; k < 64; k++) {
            float4 a0 = *(const float4*)&As[k][m0];
            float4 a1 = *(const float4*)&As[k][m0 + 4];
            float4 b4 = *(const float4*)&Bs[k][n0];
            float av[8] = {a0.x, a0.y, a0.z, a0.w, a1.x, a1.y, a1.z, a1.w};
            float bv[4] = {b4.x, b4.y, b4.z, b4.w};
#pragma unroll
            for (int i = 0; i < 8; i++)
#pragma unroll
                for (int j = 0; j < 4; j++) acc[i][j] = fmaf(av[i], bv[j], acc[i][j]);
        }
        __syncthreads();
    }

    float a1c[4], a2c[4];
#pragma unroll
    for (int j = 0; j < 4; j++) {
        a1c[j] = a[n0 + j];
        a2c[j] = a[FOUT + n0 + j];
    }

#pragma unroll
    for (int i = 0; i < 8; i++) {
        int r = block_row + m0 + i;
        float p1 = acc[i][0] * a1c[0] + acc[i][1] * a1c[1] +
                   acc[i][2] * a1c[2] + acc[i][3] * a1c[3];
        float p2 = acc[i][0] * a2c[0] + acc[i][1] * a2c[1] +
                   acc[i][2] * a2c[2] + acc[i][3] * a2c[3];
#pragma unroll
        for (int o = 8; o > 0; o >>= 1) {
            p1 += __shfl_xor_sync(0xffffffffu, p1, o);
            p2 += __shfl_xor_sync(0xffffffffu, p2, o);
        }
        if (r < TOTAL_ROWS) {
            *(float4*)&g_h[(size_t)r * FOUT + n0] =
                make_float4(acc[i][0], acc[i][1], acc[i][2], acc[i][3]);
            if (tx == 0) {
                g_f1[r] = p1;
                g_f2[r] = p2;
            }
        }
    }
}

// ---------------- histogram of src -------------------------------------------
__global__ void hist_kernel(const int* __restrict__ edges) {
    int idx = blockIdx.x * blockDim.x + threadIdx.x;
    if (idx >= B * E) return;
    int b = idx / E;
    int e = idx - b * E;
    int src = edges[(size_t)b * 2 * E + e];
    atomicAdd(&g_counts[b * N + src], 1);
}

// ---------------- scan phase A -------------------------------------------------
__global__ __launch_bounds__(256) void scanA_kernel() {
    const int b = blockIdx.x / NCHUNK;
    const int c = blockIdx.x - b * NCHUNK;
    const int tid = threadIdx.x;
    const int lane = tid & 31, wid = tid >> 5;
    __shared__ int wsum[8];
    __shared__ int blk_total;

    int base = c * 1024 + tid * 4;
    int v[4];
#pragma unroll
    for (int k = 0; k < 4; k++) {
        int i = base + k;
        v[k] = (i < N) ? g_counts[b * N + i] : 0;
    }
    int s1 = v[0] + v[1];
    int s2 = s1 + v[2];
    int tsum = s2 + v[3];

    int x = tsum;
#pragma unroll
    for (int o = 1; o < 32; o <<= 1) {
        int y = __shfl_up_sync(0xffffffffu, x, o);
        if (lane >= o) x += y;
    }
    if (lane == 31) wsum[wid] = x;
    __syncthreads();
    if (tid < 8) {
        int ws = wsum[tid];
#pragma unroll
        for (int o = 1; o < 8; o <<= 1) {
            int y = __shfl_up_sync(0xffu, ws, o);
            if (tid >= o) ws += y;
        }
        wsum[tid] = ws;
        if (tid == 7) blk_total = ws;
    }
    __syncthreads();
    int excl = (wid > 0 ? wsum[wid - 1] : 0) + (x - tsum);

    int outv[4] = {excl, excl + v[0], excl + s1, excl + s2};
#pragma unroll
    for (int k = 0; k < 4; k++) {
        int i = base + k;
        if (i < N) g_offsets[b * (N + 1) + i] = outv[k];
    }
    if (tid == 0) g_chunksum[b * NCHUNK + c] = blk_total;
}

// ---------------- scan phase B -------------------------------------------------
__global__ __launch_bounds__(64) void scanB_kernel() {
    const int b = blockIdx.x;
    const int tid = threadIdx.x;
    const int lane = tid & 31, wid = tid >> 5;
    __shared__ int w0sum;
    int v = (tid < NCHUNK) ? g_chunksum[b * NCHUNK + tid] : 0;
    int x = v;
#pragma unroll
    for (int o = 1; o < 32; o <<= 1) {
        int y = __shfl_up_sync(0xffffffffu, x, o);
        if (lane >= o) x += y;
    }
    if (tid == 31) w0sum = x;
    __syncthreads();
    if (wid == 1) x += w0sum;
    if (tid < NCHUNK) g_chunkbase[b * NCHUNK + tid] = x - v;
    if (tid == NCHUNK - 1) g_offsets[b * (N + 1) + N] = x;
}

// ---------------- scan phase C -------------------------------------------------
__global__ __launch_bounds__(256) void scanC_kernel() {
    const int b = blockIdx.x / NCHUNK;
    const int c = blockIdx.x - b * NCHUNK;
    const int tid = threadIdx.x;
    int base = g_chunkbase[b * NCHUNK + c];
    int i0 = c * 1024 + tid * 4;
#pragma unroll
    for (int k = 0; k < 4; k++) {
        int i = i0 + k;
        if (i < N) {
            int o = g_offsets[b * (N + 1) + i] + base;
            g_offsets[b * (N + 1) + i] = o;
            g_cursor[b * N + i] = o;
        }
    }
}

// ---------------- scatter dst into CSR buckets --------------------------------
__global__ void scatter_kernel(const int* __restrict__ edges) {
    int idx = blockIdx.x * blockDim.x + threadIdx.x;
    if (idx >= B * E) return;
    int b = idx / E;
    int e = idx - b * E;
    int src = edges[(size_t)b * 2 * E + e];
    int dst = edges[(size_t)b * 2 * E + E + e];
    int pos = atomicAdd(&g_cursor[b * N + src], 1);
    g_sorted_dst[(size_t)b * E + pos] = dst;
}

// ---------------- aggregation: warp per (b,node), half-warp per edge ----------
__global__ __launch_bounds__(256) void aggregate_kernel(float* __restrict__ out) {
    int w = (blockIdx.x * blockDim.x + threadIdx.x) >> 5;
    int lane = threadIdx.x & 31;
    if (w >= B * N) return;
    int b = w / N;
    int i = w - b * N;
    int half = lane >> 4;          // 0 or 1
    int hl = lane & 15;            // lane within half

    int start = g_offsets[b * (N + 1) + i];
    int end   = g_offsets[b * (N + 1) + i + 1];
    float f1i = g_f1[w];

    const float4* __restrict__ hb4 = (const float4*)(g_h + (size_t)b * N * FOUT);
    const float*  __restrict__ f2b = g_f2 + (size_t)b * N;
    const int*    __restrict__ sd  = g_sorted_dst + (size_t)b * E;

    float4 acc = make_float4(0.f, 0.f, 0.f, 0.f);
    float rowsum = 0.0f;

    for (int e = start; e < end; e += 32) {
        int cnt = end - e;
        if (cnt > 32) cnt = 32;
        bool act = lane < cnt;
        int   myDst = act ? sd[e + lane] : 0;
        float s = f1i + (act ? f2b[myDst] : 0.0f);
        float t = (s > 0.0f) ? s : ALPHA * s;
        float myWe = act ? __expf(-t) : 0.0f;
        float wsum = myWe;
#pragma unroll
        for (int o = 16; o > 0; o >>= 1) wsum += __shfl_xor_sync(0xffffffffu, wsum, o);
        rowsum += wsum;
        // two edges per iteration: lanes 0-15 -> edge j, lanes 16-31 -> edge j+1
        for (int j = 0; j < cnt; j += 2) {
            int bl = j + half;                         // broadcast lane (< 32)
            float we  = __shfl_sync(0xffffffffu, myWe, bl);
            int   dst = __shfl_sync(0xffffffffu, myDst, bl);
            float4 hv = hb4[(size_t)dst * 16 + hl];
            acc.x = fmaf(we, hv.x, acc.x);
            acc.y = fmaf(we, hv.y, acc.y);
            acc.z = fmaf(we, hv.z, acc.z);
            acc.w = fmaf(we, hv.w, acc.w);
        }
    }

    // combine the two halves
    acc.x += __shfl_down_sync(0xffffffffu, acc.x, 16);
    acc.y += __shfl_down_sync(0xffffffffu, acc.y, 16);
    acc.z += __shfl_down_sync(0xffffffffu, acc.z, 16);
    acc.w += __shfl_down_sync(0xffffffffu, acc.w, 16);

    if (half == 0) {
        float inv = 1.0f / rowsum;
        float r[4] = {acc.x * inv, acc.y * inv, acc.z * inv, acc.w * inv};
#pragma unroll
        for (int k = 0; k < 4; k++) {
            if (isnan(r[k])) r[k] = NEG_BIG;
            r[k] = (r[k] > 0.0f) ? r[k] : expm1f(r[k]);
        }
        ((float4*)out)[(size_t)w * 16 + hl] = make_float4(r[0], r[1], r[2], r[3]);
    }
}

// ---------------- launch: fork edge-prep || gemm, join, aggregate -------------
extern "C" void kernel_launch(void* const* d_in, const int* in_sizes, int n_in,
                              void* d_out, int out_size) {
    const float* X     = (const float*)d_in[0];   // (B, N, FIN)
    const int*   edges = (const int*)d_in[1];     // (B, 2, E)
    const float* W     = (const float*)d_in[2];   // (FIN, FOUT)
    const float* a     = (const float*)d_in[3];   // (1, 2*FOUT)
    float* out = (float*)d_out;                   // (B, N, FOUT)

    // lazily created side streams + events (host resources only; no device mem)
    static cudaStream_t s1 = nullptr, s2 = nullptr;
    static cudaEvent_t evFork = nullptr, evJ1 = nullptr, evJ2 = nullptr;
    if (!s1) {
        cudaStreamCreateWithFlags(&s1, cudaStreamNonBlocking);
        cudaStreamCreateWithFlags(&s2, cudaStreamNonBlocking);
        cudaEventCreateWithFlags(&evFork, cudaEventDisableTiming);
        cudaEventCreateWithFlags(&evJ1, cudaEventDisableTiming);
        cudaEventCreateWithFlags(&evJ2, cudaEventDisableTiming);
    }

    // fork from the (captured) default stream
    cudaEventRecord(evFork, 0);
    cudaStreamWaitEvent(s1, evFork, 0);
    cudaStreamWaitEvent(s2, evFork, 0);

    // branch 1: edge preparation (CSR build)
    zero_counts_kernel<<<(B * N + 255) / 256, 256, 0, s1>>>();
    hist_kernel<<<(B * E + 255) / 256, 256, 0, s1>>>(edges);
    scanA_kernel<<<B * NCHUNK, 256, 0, s1>>>();
    scanB_kernel<<<B, 64, 0, s1>>>();
    scanC_kernel<<<B * NCHUNK, 256, 0, s1>>>();
    scatter_kernel<<<(B * E + 255) / 256, 256, 0, s1>>>(edges);

    // branch 2: projection GEMM + attention dots
    gemm_f12_kernel<<<(TOTAL_ROWS + 127) / 128, 256, 0, s2>>>(X, W, a);

    // join
    cudaEventRecord(evJ1, s1);
    cudaEventRecord(evJ2, s2);
    cudaStreamWaitEvent(0, evJ1, 0);
    cudaStreamWaitEvent(0, evJ2, 0);

    // aggregate + normalize + elu
    aggregate_kernel<<<(B * N * 32 + 255) / 256, 256>>>(out);
}

// round 4
// speedup vs baseline: 1.3040x; 1.0303x over previous
#include <cuda_runtime.h>
#include <cuda_bf16.h>
#include <math.h>

#define B 4
#define N 50000
#define E 800000
#define FIN 128
#define FOUT 64
#define ALPHA 0.2f
#define NEG_BIG (-9000000000000000.0f)

#define NCHUNK 49              // ceil(50000/1024)
#define TOTAL_ROWS (B * N)     // 200000
#define GM_TILE 256            // gemm rows per block

#define PACK_F32X2(out, lo, hi) \
    asm("mov.b64 %0, {%1, %2};" : "=l"(out) : "f"(lo), "f"(hi))
#define UNPACK_F32X2(lo, hi, in) \
    asm("mov.b64 {%0, %1}, %2;" : "=f"(lo), "=f"(hi) : "l"(in))
#define FMA_F32X2(d, a, b, c) \
    asm("fma.rn.f32x2 %0, %1, %2, %3;" : "=l"(d) : "l"(a), "l"(b), "l"(c))

// ---------------- device scratch (static globals; no allocation) -------------
__device__ float g_h[(size_t)B * N * FOUT];        // 51.2 MB  projected features
__device__ float g_f1[B * N];
__device__ float g_f2[B * N];
__device__ int   g_counts[B * N];                  // zero-init at load; re-zeroed each pass
__device__ int   g_offsets[B * (N + 1)];
__device__ int   g_cursor[B * N];
__device__ int   g_sorted_dst[(size_t)B * E];
__device__ int   g_chunksum[B * NCHUNK];

// ---------------- GEMM (256x64 tile, 8x8 micro, f32x2 FMA) + fused f1/f2 ------
__global__ __launch_bounds__(256) void gemm_f12_kernel(const float* __restrict__ X,
                                                       const float* __restrict__ W,
                                                       const float* __restrict__ a) {
    extern __shared__ float smem[];
    float* As = smem;              // [64][256]
    float* Bs = smem + 64 * 256;   // [64][64]

    const int tid = threadIdx.x;
    const int block_row = blockIdx.x * GM_TILE;
    const int tx = tid & 7;                          // n0 = tx*8
    const int ty = tid >> 3;                         // 0..31, m0 = ty*8
    const int n0 = tx * 8;
    const int m0 = ty * 8;

    unsigned long long accp[4][8];                   // 4 m-pairs x 8 n
#pragma unroll
    for (int i = 0; i < 4; i++)
#pragma unroll
        for (int j = 0; j < 8; j++) accp[i][j] = 0ULL;

    const float4* X4 = (const float4*)X;   // row: 32 float4
    const float4* W4 = (const float4*)W;

    for (int kt = 0; kt < 2; kt++) {
        // A tile: 256 rows x 64 k = 4096 float4, 16 per thread (transposed)
#pragma unroll
        for (int it = 0; it < 16; it++) {
            int i = tid + it * 256;                  // 0..4095
            int row = i & 255;
            int kq  = i >> 8;                        // 0..15
            int rg  = block_row + row;
            if (rg > TOTAL_ROWS - 1) rg = TOTAL_ROWS - 1;
            float4 v = X4[(size_t)rg * 32 + kt * 16 + kq];
            As[(kq * 4 + 0) * 256 + row] = v.x;
            As[(kq * 4 + 1) * 256 + row] = v.y;
            As[(kq * 4 + 2) * 256 + row] = v.z;
            As[(kq * 4 + 3) * 256 + row] = v.w;
        }
        // B tile: 64x64 = 1024 float4, 4 per thread
#pragma unroll
        for (int it = 0; it < 4; it++) {
            int i = tid + it * 256;
            ((float4*)Bs)[i] = W4[kt * 1024 + i];
        }
        __syncthreads();

#pragma unroll 2
        for (int k = 0; k < 64; k++) {
            float4 a0 = *(const float4*)&As[k * 256 + m0];
            float4 a1 = *(const float4*)&As[k * 256 + m0 + 4];
            float4 b0 = *(const float4*)&Bs[k * 64 + n0];
            float4 b1 = *(const float4*)&Bs[k * 64 + n0 + 4];
            unsigned long long ap[4], bp[8];
            PACK_F32X2(ap[0], a0.x, a0.y);
            PACK_F32X2(ap[1], a0.z, a0.w);
            PACK_F32X2(ap[2], a1.x, a1.y);
            PACK_F32X2(ap[3], a1.z, a1.w);
            PACK_F32X2(bp[0], b0.x, b0.x);
            PACK_F32X2(bp[1], b0.y, b0.y);
            PACK_F32X2(bp[2], b0.z, b0.z);
            PACK_F32X2(bp[3], b0.w, b0.w);
            PACK_F32X2(bp[4], b1.x, b1.x);
            PACK_F32X2(bp[5], b1.y, b1.y);
            PACK_F32X2(bp[6], b1.z, b1.z);
            PACK_F32X2(bp[7], b1.w, b1.w);
#pragma unroll
            for (int i = 0; i < 4; i++)
#pragma unroll
                for (int j = 0; j < 8; j++)
                    FMA_F32X2(accp[i][j], ap[i], bp[j], accp[i][j]);
        }
        __syncthreads();
    }

    // unpack accumulators: accf[i][j] = h[block_row+m0+i][n0+j]
    float accf[8][8];
#pragma unroll
    for (int i = 0; i < 4; i++)
#pragma unroll
        for (int j = 0; j < 8; j++)
            UNPACK_F32X2(accf[2 * i][j], accf[2 * i + 1][j], accp[i][j]);

    float a1c[8], a2c[8];
#pragma unroll
    for (int j = 0; j < 8; j++) {
        a1c[j] = a[n0 + j];
        a2c[j] = a[FOUT + n0 + j];
    }

#pragma unroll
    for (int i = 0; i < 8; i++) {
        int r = block_row + m0 + i;
        float p1 = 0.f, p2 = 0.f;
#pragma unroll
        for (int j = 0; j < 8; j++) {
            p1 = fmaf(accf[i][j], a1c[j], p1);
            p2 = fmaf(accf[i][j], a2c[j], p2);
        }
        // reduce across the 8 tx lanes (consecutive lanes within warp)
#pragma unroll
        for (int o = 4; o > 0; o >>= 1) {
            p1 += __shfl_xor_sync(0xffffffffu, p1, o);
            p2 += __shfl_xor_sync(0xffffffffu, p2, o);
        }
        if (r < TOTAL_ROWS) {
            *(float4*)&g_h[(size_t)r * FOUT + n0] =
                make_float4(accf[i][0], accf[i][1], accf[i][2], accf[i][3]);
            *(float4*)&g_h[(size_t)r * FOUT + n0 + 4] =
                make_float4(accf[i][4], accf[i][5], accf[i][6], accf[i][7]);
            if (tx == 0) {
                g_f1[r] = p1;
                g_f2[r] = p2;
            }
        }
    }
}

// ---------------- histogram of src (counts pre-zeroed by previous pass) -------
__global__ void hist_kernel(const int* __restrict__ edges) {
    int idx = blockIdx.x * blockDim.x + threadIdx.x;
    if (idx >= B * E) return;
    int b = idx / E;
    int e = idx - b * E;
    int src = edges[(size_t)b * 2 * E + e];
    atomicAdd(&g_counts[b * N + src], 1);
}

// ---------------- scan phase A: per-chunk local exclusive scan ----------------
__global__ __launch_bounds__(256) void scanA_kernel() {
    const int b = blockIdx.x / NCHUNK;
    const int c = blockIdx.x - b * NCHUNK;
    const int tid = threadIdx.x;
    const int lane = tid & 31, wid = tid >> 5;
    __shared__ int wsum[8];
    __shared__ int blk_total;

    int base = c * 1024 + tid * 4;
    int v[4];
#pragma unroll
    for (int k = 0; k < 4; k++) {
        int i = base + k;
        v[k] = (i < N) ? g_counts[b * N + i] : 0;
    }
    int s1 = v[0] + v[1];
    int s2 = s1 + v[2];
    int tsum = s2 + v[3];

    int x = tsum;
#pragma unroll
    for (int o = 1; o < 32; o <<= 1) {
        int y = __shfl_up_sync(0xffffffffu, x, o);
        if (lane >= o) x += y;
    }
    if (lane == 31) wsum[wid] = x;
    __syncthreads();
    if (tid < 8) {
        int ws = wsum[tid];
#pragma unroll
        for (int o = 1; o < 8; o <<= 1) {
            int y = __shfl_up_sync(0xffu, ws, o);
            if (tid >= o) ws += y;
        }
        wsum[tid] = ws;
        if (tid == 7) blk_total = ws;
    }
    __syncthreads();
    int excl = (wid > 0 ? wsum[wid - 1] : 0) + (x - tsum);

    int outv[4] = {excl, excl + v[0], excl + s1, excl + s2};
#pragma unroll
    for (int k = 0; k < 4; k++) {
        int i = base + k;
        if (i < N) g_offsets[b * (N + 1) + i] = outv[k];
    }
    if (tid == 0) g_chunksum[b * NCHUNK + c] = blk_total;
}

// ---------------- scan phase C: local chunk-sum scan + apply + reset counts ---
__global__ __launch_bounds__(256) void scanC_kernel() {
    const int b = blockIdx.x / NCHUNK;
    const int c = blockIdx.x - b * NCHUNK;
    const int tid = threadIdx.x;
    const int lane = tid & 31, wid = tid >> 5;
    __shared__ int w0s;
    __shared__ int sbase;

    int v = 0;
    if (tid < NCHUNK) v = g_chunksum[b * NCHUNK + tid];
    int x = v;
#pragma unroll
    for (int o = 1; o < 32; o <<= 1) {
        int y = __shfl_up_sync(0xffffffffu, x, o);
        if (lane >= o) x += y;
    }
    if (tid == 31) w0s = x;
    __syncthreads();
    if (wid == 1) x += w0s;
    if (tid == c) sbase = x - v;                   // exclusive prefix for this chunk
    if (tid == NCHUNK - 1 && c == NCHUNK - 1)
        g_offsets[b * (N + 1) + N] = x;            // grand total
    __syncthreads();

    int base = sbase;
    int i0 = c * 1024 + tid * 4;
#pragma unroll
    for (int k = 0; k < 4; k++) {
        int i = i0 + k;
        if (i < N) {
            int o = g_offsets[b * (N + 1) + i] + base;
            g_offsets[b * (N + 1) + i] = o;
            g_cursor[b * N + i] = o;
            g_counts[b * N + i] = 0;               // reset for next pass
        }
    }
}

// ---------------- scatter dst into CSR buckets --------------------------------
__global__ void scatter_kernel(const int* __restrict__ edges) {
    int idx = blockIdx.x * blockDim.x + threadIdx.x;
    if (idx >= B * E) return;
    int b = idx / E;
    int e = idx - b * E;
    int src = edges[(size_t)b * 2 * E + e];
    int dst = edges[(size_t)b * 2 * E + E + e];
    int pos = atomicAdd(&g_cursor[b * N + src], 1);
    g_sorted_dst[(size_t)b * E + pos] = dst;
}

// ---------------- aggregation: warp per (b,node), half-warp per edge ----------
__global__ __launch_bounds__(256) void aggregate_kernel(float* __restrict__ out) {
    int w = (blockIdx.x * blockDim.x + threadIdx.x) >> 5;
    int lane = threadIdx.x & 31;
    if (w >= B * N) return;
    int b = w / N;
    int i = w - b * N;
    int half = lane >> 4;          // 0 or 1
    int hl = lane & 15;            // lane within half

    int start = g_offsets[b * (N + 1) + i];
    int end   = g_offsets[b * (N + 1) + i + 1];
    float f1i = g_f1[w];

    const float4* __restrict__ hb4 = (const float4*)(g_h + (size_t)b * N * FOUT);
    const float*  __restrict__ f2b = g_f2 + (size_t)b * N;
    const int*    __restrict__ sd  = g_sorted_dst + (size_t)b * E;

    float4 acc = make_float4(0.f, 0.f, 0.f, 0.f);
    float rowsum = 0.0f;           // per-half accumulation of edge weights

    for (int e = start; e < end; e += 32) {
        int cnt = end - e;
        if (cnt > 32) cnt = 32;
        bool act = lane < cnt;
        int   myDst = act ? sd[e + lane] : 0;
        float s = f1i + (act ? f2b[myDst] : 0.0f);
        float t = (s > 0.0f) ? s : ALPHA * s;
        float myWe = act ? __expf(-t) : 0.0f;
        // two edges per iteration: half 0 -> edge j, half 1 -> edge j+1
        for (int j = 0; j < cnt; j += 2) {
            int bl = j + half;
            float we  = __shfl_sync(0xffffffffu, myWe, bl);
            int   dst = __shfl_sync(0xffffffffu, myDst, bl);
            float4 hv = hb4[(size_t)dst * 16 + hl];
            rowsum += we;                          // counted 16x per half; fixed below
            acc.x = fmaf(we, hv.x, acc.x);
            acc.y = fmaf(we, hv.y, acc.y);
            acc.z = fmaf(we, hv.z, acc.z);
            acc.w = fmaf(we, hv.w, acc.w);
        }
    }

    // combine the two halves (rowsum: each half summed its own edges' weights)
    acc.x += __shfl_down_sync(0xffffffffu, acc.x, 16);
    acc.y += __shfl_down_sync(0xffffffffu, acc.y, 16);
    acc.z += __shfl_down_sync(0xffffffffu, acc.z, 16);
    acc.w += __shfl_down_sync(0xffffffffu, acc.w, 16);
    rowsum += __shfl_down_sync(0xffffffffu, rowsum, 16);

    if (half == 0) {
        float inv = 1.0f / rowsum;
        float r[4] = {acc.x * inv, acc.y * inv, acc.z * inv, acc.w * inv};
#pragma unroll
        for (int k = 0; k < 4; k++) {
            if (isnan(r[k])) r[k] = NEG_BIG;
            r[k] = (r[k] > 0.0f) ? r[k] : expm1f(r[k]);
        }
        ((float4*)out)[(size_t)w * 16 + hl] = make_float4(r[0], r[1], r[2], r[3]);
    }
}

// ---------------- launch: fork edge-prep || gemm, join, aggregate -------------
extern "C" void kernel_launch(void* const* d_in, const int* in_sizes, int n_in,
                              void* d_out, int out_size) {
    const float* X     = (const float*)d_in[0];   // (B, N, FIN)
    const int*   edges = (const int*)d_in[1];     // (B, 2, E)
    const float* W     = (const float*)d_in[2];   // (FIN, FOUT)
    const float* a     = (const float*)d_in[3];   // (1, 2*FOUT)
    float* out = (float*)d_out;                   // (B, N, FOUT)

    static cudaStream_t s1 = nullptr, s2 = nullptr;
    static cudaEvent_t evFork = nullptr, evJ1 = nullptr, evJ2 = nullptr;
    if (!s1) {
        cudaStreamCreateWithFlags(&s1, cudaStreamNonBlocking);
        cudaStreamCreateWithFlags(&s2, cudaStreamNonBlocking);
        cudaEventCreateWithFlags(&evFork, cudaEventDisableTiming);
        cudaEventCreateWithFlags(&evJ1, cudaEventDisableTiming);
        cudaEventCreateWithFlags(&evJ2, cudaEventDisableTiming);
        cudaFuncSetAttribute(gemm_f12_kernel,
                             cudaFuncAttributeMaxDynamicSharedMemorySize,
                             (64 * 256 + 64 * 64) * 4);
    }

    cudaEventRecord(evFork, 0);
    cudaStreamWaitEvent(s1, evFork, 0);
    cudaStreamWaitEvent(s2, evFork, 0);

    // branch 1: edge preparation (CSR build); counts arrive zeroed
    hist_kernel<<<(B * E + 255) / 256, 256, 0, s1>>>(edges);
    scanA_kernel<<<B * NCHUNK, 256, 0, s1>>>();
    scanC_kernel<<<B * NCHUNK, 256, 0, s1>>>();
    scatter_kernel<<<(B * E + 255) / 256, 256, 0, s1>>>(edges);

    // branch 2: projection GEMM + attention dots (f32x2 packed FMA)
    gemm_f12_kernel<<<(TOTAL_ROWS + GM_TILE - 1) / GM_TILE, 256,
                      (64 * 256 + 64 * 64) * 4, s2>>>(X, W, a);

    // join
    cudaEventRecord(evJ1, s1);
    cudaEventRecord(evJ2, s2);
    cudaStreamWaitEvent(0, evJ1, 0);
    cudaStreamWaitEvent(0, evJ2, 0);

    // aggregate + normalize + elu
    aggregate_kernel<<<(B * N * 32 + 255) / 256, 256>>>(out);
}

// round 6
// speedup vs baseline: 1.3223x; 1.0140x over previous
#include <cuda_runtime.h>
#include <cuda_bf16.h>
#include <math.h>

#define B 4
#define N 50000
#define E 800000
#define FIN 128
#define FOUT 64
#define ALPHA 0.2f
#define NEG_BIG (-9000000000000000.0f)

#define NCHUNK 49              // ceil(50000/1024)
#define GM_TILE 256            // gemm rows per block
#define GM_BLOCKS ((N + GM_TILE - 1) / GM_TILE)   // 196 per batch

#define PACK_F32X2(out, lo, hi) \
    asm("mov.b64 %0, {%1, %2};" : "=l"(out) : "f"(lo), "f"(hi))
#define UNPACK_F32X2(lo, hi, in) \
    asm("mov.b64 {%0, %1}, %2;" : "=f"(lo), "=f"(hi) : "l"(in))
#define FMA_F32X2(d, a, b, c) \
    asm("fma.rn.f32x2 %0, %1, %2, %3;" : "=l"(d) : "l"(a), "l"(b), "l"(c))

// ---------------- device scratch (static globals; no allocation) -------------
__device__ float g_h[(size_t)B * N * FOUT];        // 51.2 MB  projected features
__device__ float g_f1[B * N];
__device__ float g_f2[B * N];
__device__ int   g_counts[B * N];                  // zero-init at load; re-zeroed each pass
__device__ int   g_offsets[B * (N + 1)];
__device__ int   g_cursor[B * N];
__device__ int   g_sorted_dst[(size_t)B * E];
__device__ int   g_chunksum[B * NCHUNK];

// ---------------- GEMM (256x64 tile, 8x8 micro, f32x2 FMA) + fused f1/f2 ------
// one batch per launch: rows [b*N, (b+1)*N)
__global__ __launch_bounds__(256) void gemm_f12_kernel(const float* __restrict__ X,
                                                       const float* __restrict__ W,
                                                       const float* __restrict__ a,
                                                       int b) {
    extern __shared__ float smem[];
    float* As = smem;              // [64][256]
    float* Bs = smem + 64 * 256;   // [64][64]

    const int tid = threadIdx.x;
    const int row_lim = (b + 1) * N;
    const int block_row = b * N + blockIdx.x * GM_TILE;
    const int tx = tid & 7;                          // n0 = tx*8
    const int ty = tid >> 3;                         // 0..31, m0 = ty*8
    const int n0 = tx * 8;
    const int m0 = ty * 8;

    unsigned long long accp[4][8];
#pragma unroll
    for (int i = 0; i < 4; i++)
#pragma unroll
        for (int j = 0; j < 8; j++) accp[i][j] = 0ULL;

    const float4* X4 = (const float4*)X;   // row: 32 float4
    const float4* W4 = (const float4*)W;

    for (int kt = 0; kt < 2; kt++) {
#pragma unroll
        for (int it = 0; it < 16; it++) {
            int i = tid + it * 256;                  // 0..4095
            int row = i & 255;
            int kq  = i >> 8;                        // 0..15
            int rg  = block_row + row;
            if (rg > row_lim - 1) rg = row_lim - 1;
            float4 v = X4[(size_t)rg * 32 + kt * 16 + kq];
            As[(kq * 4 + 0) * 256 + row] = v.x;
            As[(kq * 4 + 1) * 256 + row] = v.y;
            As[(kq * 4 + 2) * 256 + row] = v.z;
            As[(kq * 4 + 3) * 256 + row] = v.w;
        }
#pragma unroll
        for (int it = 0; it < 4; it++) {
            int i = tid + it * 256;
            ((float4*)Bs)[i] = W4[kt * 1024 + i];
        }
        __syncthreads();

#pragma unroll 2
        for (int k = 0; k < 64; k++) {
            float4 a0 = *(const float4*)&As[k * 256 + m0];
            float4 a1 = *(const float4*)&As[k * 256 + m0 + 4];
            float4 b0 = *(const float4*)&Bs[k * 64 + n0];
            float4 b1 = *(const float4*)&Bs[k * 64 + n0 + 4];
            unsigned long long ap[4], bp[8];
            PACK_F32X2(ap[0], a0.x, a0.y);
            PACK_F32X2(ap[1], a0.z, a0.w);
            PACK_F32X2(ap[2], a1.x, a1.y);
            PACK_F32X2(ap[3], a1.z, a1.w);
            PACK_F32X2(bp[0], b0.x, b0.x);
            PACK_F32X2(bp[1], b0.y, b0.y);
            PACK_F32X2(bp[2], b0.z, b0.z);
            PACK_F32X2(bp[3], b0.w, b0.w);
            PACK_F32X2(bp[4], b1.x, b1.x);
            PACK_F32X2(bp[5], b1.y, b1.y);
            PACK_F32X2(bp[6], b1.z, b1.z);
            PACK_F32X2(bp[7], b1.w, b1.w);
#pragma unroll
            for (int i = 0; i < 4; i++)
#pragma unroll
                for (int j = 0; j < 8; j++)
                    FMA_F32X2(accp[i][j], ap[i], bp[j], accp[i][j]);
        }
        __syncthreads();
    }

    float accf[8][8];
#pragma unroll
    for (int i = 0; i < 4; i++)
#pragma unroll
        for (int j = 0; j < 8; j++)
            UNPACK_F32X2(accf[2 * i][j], accf[2 * i + 1][j], accp[i][j]);

    float a1c[8], a2c[8];
#pragma unroll
    for (int j = 0; j < 8; j++) {
        a1c[j] = a[n0 + j];
        a2c[j] = a[FOUT + n0 + j];
    }

#pragma unroll
    for (int i = 0; i < 8; i++) {
        int r = block_row + m0 + i;
        float p1 = 0.f, p2 = 0.f;
#pragma unroll
        for (int j = 0; j < 8; j++) {
            p1 = fmaf(accf[i][j], a1c[j], p1);
            p2 = fmaf(accf[i][j], a2c[j], p2);
        }
#pragma unroll
        for (int o = 4; o > 0; o >>= 1) {
            p1 += __shfl_xor_sync(0xffffffffu, p1, o);
            p2 += __shfl_xor_sync(0xffffffffu, p2, o);
        }
        if (r < row_lim) {
            *(float4*)&g_h[(size_t)r * FOUT + n0] =
                make_float4(accf[i][0], accf[i][1], accf[i][2], accf[i][3]);
            *(float4*)&g_h[(size_t)r * FOUT + n0 + 4] =
                make_float4(accf[i][4], accf[i][5], accf[i][6], accf[i][7]);
            if (tx == 0) {
                g_f1[r] = p1;
                g_f2[r] = p2;
            }
        }
    }
}

// ---------------- histogram of src (per batch) ---------------------------------
__global__ void hist_kernel(const int* __restrict__ edges, int b) {
    int e = blockIdx.x * blockDim.x + threadIdx.x;
    if (e >= E) return;
    int src = edges[(size_t)b * 2 * E + e];
    atomicAdd(&g_counts[b * N + src], 1);
}

// ---------------- scan phase A (per batch) --------------------------------------
__global__ __launch_bounds__(256) void scanA_kernel(int b) {
    const int c = blockIdx.x;
    const int tid = threadIdx.x;
    const int lane = tid & 31, wid = tid >> 5;
    __shared__ int wsum[8];
    __shared__ int blk_total;

    int base = c * 1024 + tid * 4;
    int v[4];
#pragma unroll
    for (int k = 0; k < 4; k++) {
        int i = base + k;
        v[k] = (i < N) ? g_counts[b * N + i] : 0;
    }
    int s1 = v[0] + v[1];
    int s2 = s1 + v[2];
    int tsum = s2 + v[3];

    int x = tsum;
#pragma unroll
    for (int o = 1; o < 32; o <<= 1) {
        int y = __shfl_up_sync(0xffffffffu, x, o);
        if (lane >= o) x += y;
    }
    if (lane == 31) wsum[wid] = x;
    __syncthreads();
    if (tid < 8) {
        int ws = wsum[tid];
#pragma unroll
        for (int o = 1; o < 8; o <<= 1) {
            int y = __shfl_up_sync(0xffu, ws, o);
            if (tid >= o) ws += y;
        }
        wsum[tid] = ws;
        if (tid == 7) blk_total = ws;
    }
    __syncthreads();
    int excl = (wid > 0 ? wsum[wid - 1] : 0) + (x - tsum);

    int outv[4] = {excl, excl + v[0], excl + s1, excl + s2};
#pragma unroll
    for (int k = 0; k < 4; k++) {
        int i = base + k;
        if (i < N) g_offsets[b * (N + 1) + i] = outv[k];
    }
    if (tid == 0) g_chunksum[b * NCHUNK + c] = blk_total;
}

// ---------------- scan phase C (per batch): chunk-sum scan + apply + reset ------
__global__ __launch_bounds__(256) void scanC_kernel(int b) {
    const int c = blockIdx.x;
    const int tid = threadIdx.x;
    const int lane = tid & 31, wid = tid >> 5;
    __shared__ int w0s;
    __shared__ int sbase;

    int v = 0;
    if (tid < NCHUNK) v = g_chunksum[b * NCHUNK + tid];
    int x = v;
#pragma unroll
    for (int o = 1; o < 32; o <<= 1) {
        int y = __shfl_up_sync(0xffffffffu, x, o);
        if (lane >= o) x += y;
    }
    if (tid == 31) w0s = x;
    __syncthreads();
    if (wid == 1) x += w0s;
    if (tid == c) sbase = x - v;
    if (tid == NCHUNK - 1 && c == NCHUNK - 1)
        g_offsets[b * (N + 1) + N] = x;
    __syncthreads();

    int base = sbase;
    int i0 = c * 1024 + tid * 4;
#pragma unroll
    for (int k = 0; k < 4; k++) {
        int i = i0 + k;
        if (i < N) {
            int o = g_offsets[b * (N + 1) + i] + base;
            g_offsets[b * (N + 1) + i] = o;
            g_cursor[b * N + i] = o;
            g_counts[b * N + i] = 0;
        }
    }
}

// ---------------- scatter dst into CSR buckets (per batch) ----------------------
__global__ void scatter_kernel(const int* __restrict__ edges, int b) {
    int e = blockIdx.x * blockDim.x + threadIdx.x;
    if (e >= E) return;
    int src = edges[(size_t)b * 2 * E + e];
    int dst = edges[(size_t)b * 2 * E + E + e];
    int pos = atomicAdd(&g_cursor[b * N + src], 1);
    g_sorted_dst[(size_t)b * E + pos] = dst;
}

// ---------------- aggregation (per batch): warp per node, half-warp per edge ----
__global__ __launch_bounds__(256) void aggregate_kernel(float* __restrict__ out, int b) {
    int i = (blockIdx.x * blockDim.x + threadIdx.x) >> 5;
    int lane = threadIdx.x & 31;
    if (i >= N) return;
    int w = b * N + i;
    int half = lane >> 4;
    int hl = lane & 15;

    int start = g_offsets[b * (N + 1) + i];
    int end   = g_offsets[b * (N + 1) + i + 1];
    float f1i = g_f1[w];

    const float4* __restrict__ hb4 = (const float4*)(g_h + (size_t)b * N * FOUT);
    const float*  __restrict__ f2b = g_f2 + (size_t)b * N;
    const int*    __restrict__ sd  = g_sorted_dst + (size_t)b * E;

    float4 acc = make_float4(0.f, 0.f, 0.f, 0.f);
    float rowsum = 0.0f;

    for (int e = start; e < end; e += 32) {
        int cnt = end - e;
        if (cnt > 32) cnt = 32;
        bool act = lane < cnt;
        int   myDst = act ? sd[e + lane] : 0;
        float s = f1i + (act ? f2b[myDst] : 0.0f);
        float t = (s > 0.0f) ? s : ALPHA * s;
        float myWe = act ? __expf(-t) : 0.0f;
        for (int j = 0; j < cnt; j += 2) {
            int bl = j + half;
            float we  = __shfl_sync(0xffffffffu, myWe, bl);
            int   dst = __shfl_sync(0xffffffffu, myDst, bl);
            float4 hv = hb4[(size_t)dst * 16 + hl];
            rowsum += we;
            acc.x = fmaf(we, hv.x, acc.x);
            acc.y = fmaf(we, hv.y, acc.y);
            acc.z = fmaf(we, hv.z, acc.z);
            acc.w = fmaf(we, hv.w, acc.w);
        }
    }

    acc.x += __shfl_down_sync(0xffffffffu, acc.x, 16);
    acc.y += __shfl_down_sync(0xffffffffu, acc.y, 16);
    acc.z += __shfl_down_sync(0xffffffffu, acc.z, 16);
    acc.w += __shfl_down_sync(0xffffffffu, acc.w, 16);
    rowsum += __shfl_down_sync(0xffffffffu, rowsum, 16);

    if (half == 0) {
        float inv = 1.0f / rowsum;
        float r[4] = {acc.x * inv, acc.y * inv, acc.z * inv, acc.w * inv};
#pragma unroll
        for (int k = 0; k < 4; k++) {
            if (isnan(r[k])) r[k] = NEG_BIG;
            r[k] = (r[k] > 0.0f) ? r[k] : expm1f(r[k]);
        }
        ((float4*)out)[(size_t)w * 16 + hl] = make_float4(r[0], r[1], r[2], r[3]);
    }
}

// ---------------- launch: 2 side streams, per-batch software pipeline ------------
extern "C" void kernel_launch(void* const* d_in, const int* in_sizes, int n_in,
                              void* d_out, int out_size) {
    const float* X     = (const float*)d_in[0];   // (B, N, FIN)
    const int*   edges = (const int*)d_in[1];     // (B, 2, E)
    const float* W     = (const float*)d_in[2];   // (FIN, FOUT)
    const float* a     = (const float*)d_in[3];   // (1, 2*FOUT)
    float* out = (float*)d_out;                   // (B, N, FOUT)

    static cudaStream_t sE = nullptr, sG = nullptr;
    static cudaEvent_t evFork = nullptr;
    static cudaEvent_t evP[B] = {}, evG[B] = {};
    if (!sE) {
        cudaStreamCreateWithFlags(&sE, cudaStreamNonBlocking);
        cudaStreamCreateWithFlags(&sG, cudaStreamNonBlocking);
        cudaEventCreateWithFlags(&evFork, cudaEventDisableTiming);
        for (int b = 0; b < B; b++) {
            cudaEventCreateWithFlags(&evP[b], cudaEventDisableTiming);
            cudaEventCreateWithFlags(&evG[b], cudaEventDisableTiming);
        }
        cudaFuncSetAttribute(gemm_f12_kernel,
                             cudaFuncAttributeMaxDynamicSharedMemorySize,
                             (64 * 256 + 64 * 64) * 4);
    }

    // fork from the (captured) default stream
    cudaEventRecord(evFork, 0);
    cudaStreamWaitEvent(sE, evFork, 0);
    cudaStreamWaitEvent(sG, evFork, 0);

    // stream sE: edge-prep pipelines, batch by batch
    for (int b = 0; b < B; b++) {
        hist_kernel<<<(E + 255) / 256, 256, 0, sE>>>(edges, b);
        scanA_kernel<<<NCHUNK, 256, 0, sE>>>(b);
        scanC_kernel<<<NCHUNK, 256, 0, sE>>>(b);
        scatter_kernel<<<(E + 255) / 256, 256, 0, sE>>>(edges, b);
        cudaEventRecord(evP[b], sE);
    }

    // stream sG: per-batch GEMMs
    for (int b = 0; b < B; b++) {
        gemm_f12_kernel<<<GM_BLOCKS, 256, (64 * 256 + 64 * 64) * 4, sG>>>(X, W, a, b);
        cudaEventRecord(evG[b], sG);
    }

    // default stream: aggregate(b) as soon as its CSR + h are ready
    for (int b = 0; b < B; b++) {
        cudaStreamWaitEvent(0, evP[b], 0);
        cudaStreamWaitEvent(0, evG[b], 0);
        aggregate_kernel<<<(N * 32 + 255) / 256, 256>>>(out, b);
    }
}